// round 15
// baseline (speedup 1.0000x reference)
#include <cuda_runtime.h>
#include <math.h>

// Shapes (fixed for this problem)
#define NB 16
#define CI 64
#define CO 64
#define HH 256
#define WW 256
#define M0 32
#define M1 32

typedef unsigned long long u64;

// Scratch (device globals; no allocation allowed in kernel_launch)
__device__ __align__(256) float g_Xw [(size_t)NB*CI*HH*M1*2]; // 67 MB  [b][i][h][l]{re,im}
__device__ __align__(256) float g_Xm [(size_t)NB*CI*M0*M1*2]; // 8.4 MB [b][i][k*32+l]{re,im}
__device__ __align__(256) float g_Yb [(size_t)NB*CO*M0*M1*2]; // 8.4 MB [b][o][k*32+l]{re,im}
__device__ __align__(256) float g_Z  [(size_t)NB*CO*HH*M1*2]; // 67 MB  [b][o][h][l]{re,im}
__device__ __align__(256) float2 g_Wt[(size_t)M0*M1*CI*CO];   // 33.5MB [kl][i*64+o]{re,im}
__device__ __align__(256) float g_gamma[NB*CO];
__device__ __align__(256) float g_beta [NB*CO];

// ---- packed fp32x2 helpers (SASS FFMA2 path; PTX-only, ptxas won't emit) ----
__device__ __forceinline__ u64 pack2(float lo, float hi) {
    u64 r; asm("mov.b64 %0, {%1, %2};" : "=l"(r) : "f"(lo), "f"(hi)); return r;
}
__device__ __forceinline__ u64 dup2(float v) { return pack2(v, v); }
__device__ __forceinline__ void fma2(u64 &d, u64 a, u64 b) {
    asm("fma.rn.f32x2 %0, %1, %2, %0;" : "+l"(d) : "l"(a), "l"(b));
}
__device__ __forceinline__ u64 add2(u64 a, u64 b) {
    u64 r; asm("add.rn.f32x2 %0, %1, %2;" : "=l"(r) : "l"(a), "l"(b)); return r;
}
__device__ __forceinline__ u64 sub2(u64 a, u64 b) {
    u64 r; asm("sub.rn.f32x2 %0, %1, %2;" : "=l"(r) : "l"(a), "l"(b)); return r;
}
__device__ __forceinline__ float2 unpk2(u64 v) {
    float2 f; asm("mov.b64 {%0, %1}, %2;" : "=f"(f.x), "=f"(f.y) : "l"(v)); return f;
}

__device__ __forceinline__ float gelu_tanh(float x) {
    float u = 0.7978845608028654f * (x + 0.044715f * x * x * x);
    float t;
    asm("tanh.approx.f32 %0, %1;" : "=f"(t) : "f"(u));
    return 0.5f * x * (1.0f + t);
}

// ---------------------------------------------------------------------------
// Stage A (merged with setup): grid 4097. f32x2 accumulation over l-pairs.
// ---------------------------------------------------------------------------
#define A3_U   0
#define A3_V   8448      // 64*132
#define A3_TC  16896
#define A3_TS  21282     // 16896 + 129*34
#define A3_SMEM (21282 + 128*34)   // 25634 floats

__global__ __launch_bounds__(256) void stageA5(const float* __restrict__ x,
                                               const float* __restrict__ wr,
                                               const float* __restrict__ wi,
                                               const float* __restrict__ t_emb,
                                               const float* __restrict__ w1,
                                               const float* __restrict__ b1,
                                               const float* __restrict__ w2,
                                               const float* __restrict__ b2) {
    extern __shared__ float sm[];
    int tid = threadIdx.x;
    int bid = blockIdx.x;
    const float TWO_PI = 6.283185307179586f;

    if (bid >= 4096) {                    // ---- FiLM block ----
        float* tsh = sm;
        float* hsh = sm + 1024;
        for (int p = tid; p < NB*CI; p += 256) tsh[p] = t_emb[p];
        __syncthreads();
        for (int p = tid; p < NB*CI; p += 256) {
            int b = p >> 6, j = p & 63;
            float s = b1[j];
            for (int i = 0; i < CI; i++) s += tsh[(b<<6)+i] * w1[i*CI + j];
            hsh[p] = s / (1.0f + expf(-s));
        }
        __syncthreads();
        for (int p = tid; p < NB*2*CO; p += 256) {
            int b = p >> 7, j = p & 127;
            float s = b2[j];
            for (int i = 0; i < CI; i++) s += hsh[(b<<6)+i] * w2[i*(2*CO) + j];
            if (j < CO) g_gamma[(b<<6)+j] = s;
            else        g_beta [(b<<6)+j-CO] = s;
        }
        return;
    }

    // ---- W-transpose side-task ----
    {
        int p0  = (bid >> 5) << 5;
        int kl0 = (bid & 31) << 5;
        for (int q = tid; q < 1024; q += 256) {
            int r = q >> 5, c = q & 31;
            float a  = wr[(size_t)(p0 + r) * 1024 + kl0 + c];
            float bv = wi[(size_t)(p0 + r) * 1024 + kl0 + c];
            g_Wt[(size_t)(kl0 + c) * 4096 + p0 + r] = make_float2(a, bv);
        }
    }

    // ---- Stage A proper ----
    float* U  = sm + A3_U;
    float* V  = sm + A3_V;
    float* Tc = sm + A3_TC;
    float* Ts = sm + A3_TS;
    int lane = tid & 31, wid = tid >> 5;
    int b = bid >> 8;
    int h = bid & 255;

    for (int p = tid; p < 129*32; p += 256) {     // tables inline, exact phase
        int w = p >> 5, l = p & 31;
        int m = (w * l) & 255;
        float s, c; sincosf(TWO_PI * (float)m * (1.0f/256.0f), &s, &c);
        Tc[w*34 + l] = c;
        if (w < 128) Ts[w*34 + l] = -s;
    }

    size_t xbase = (size_t)b * CI * HH * WW + (size_t)h * WW;
    for (int i = wid; i < 64; i += 8) {
        const float4* xr = (const float4*)(x + xbase + (size_t)i * HH * WW);
        float4 A4 = xr[lane];
        float4 B4 = xr[63 - lane];
        float m0 = __shfl_up_sync(0xffffffffu, B4.x, 1);
        float4 u, v;
        if (lane == 0) { u.x = A4.x;      v.x = 0.0f; }
        else           { u.x = A4.x + m0; v.x = A4.x - m0; }
        u.y = A4.y + B4.w;  v.y = A4.y - B4.w;
        u.z = A4.z + B4.z;  v.z = A4.z - B4.z;
        u.w = A4.w + B4.y;  v.w = A4.w - B4.y;
        *(float4*)&U[i*132 + 4*lane] = u;
        *(float4*)&V[i*132 + 4*lane] = v;
        if (lane == 31) U[i*132 + 128] = B4.x;
    }
    __syncthreads();

    int i0 = (tid >> 4) << 2;
    int l0 = (tid & 15) << 1;
    u64 re2[4], im2[4];
#pragma unroll
    for (int r = 0; r < 4; r++) { re2[r] = 0ULL; im2[r] = 0ULL; }

    const float* U0  = U + i0*132;
    const float* V0  = V + i0*132;
    const float* Tcp = Tc + l0;
    const float* Tsp = Ts + l0;
#pragma unroll 3
    for (int w = 0; w < 129; w++) {
        u64 cd = *(const u64*)&Tcp[w*34];            // packed (cos_l0, cos_l0+1)
        fma2(re2[0], cd, dup2(U0[w]));
        fma2(re2[1], cd, dup2(U0[132+w]));
        fma2(re2[2], cd, dup2(U0[264+w]));
        fma2(re2[3], cd, dup2(U0[396+w]));
    }
#pragma unroll 4
    for (int w = 0; w < 128; w++) {
        u64 sd = *(const u64*)&Tsp[w*34];            // packed (-sin_l0, -sin_l0+1)
        fma2(im2[0], sd, dup2(V0[w]));
        fma2(im2[1], sd, dup2(V0[132+w]));
        fma2(im2[2], sd, dup2(V0[264+w]));
        fma2(im2[3], sd, dup2(V0[396+w]));
    }
#pragma unroll
    for (int r = 0; r < 4; r++) {
        float2 rr = unpk2(re2[r]);
        float2 mm = unpk2(im2[r]);
        size_t idx = (((size_t)(b*64 + i0 + r) * 256 + h) * 64) + 2*l0;
        *(float4*)&g_Xw[idx] = make_float4(rr.x, mm.x, rr.y, mm.y);
    }
}

// ---------------------------------------------------------------------------
// Stage B (f32x2 + h-parity fold).
// ---------------------------------------------------------------------------
__global__ __launch_bounds__(256) void stageB() {
    __shared__ ulonglong2 twp[256];   // 4 KB
    int tid = threadIdx.x;
    { float s, c; sincosf(6.283185307179586f * (float)tid * (1.0f/256.0f), &s, &c);
      twp[tid] = make_ulonglong2(pack2(c, -s), pack2(s, c)); }
    __syncthreads();
    int blk = blockIdx.x;                             // b*64+i
    const float2* Xp = (const float2*)(g_Xw) + (size_t)blk * HH * M1;
    int l  = tid & 31;
    int k0 = tid >> 5;
    float sg = (k0 & 1) ? -1.0f : 1.0f;               // (-1)^k, warp-uniform
    u64 acc2[4];
    int mt[4];
#pragma unroll
    for (int t = 0; t < 4; t++) { acc2[t] = 0ULL; mt[t] = 0; }
    for (int h = 0; h < 128; h++) {
        float2 xa = Xp[h*M1 + l];
        float2 xb = Xp[(h+128)*M1 + l];
        u64 zr2 = dup2(fmaf(sg, xb.x, xa.x));
        u64 zi2 = dup2(fmaf(sg, xb.y, xa.y));
#pragma unroll
        for (int t = 0; t < 4; t++) {
            ulonglong2 e = twp[mt[t]];                // broadcast LDS.128
            fma2(acc2[t], e.x, zr2);
            fma2(acc2[t], e.y, zi2);
            mt[t] = (mt[t] + k0 + (t << 3)) & 255;
        }
    }
    float2* Om = (float2*)g_Xm + (size_t)blk * (M0*M1);
#pragma unroll
    for (int t = 0; t < 4; t++) {
        int k = k0 + (t << 3);
        Om[k*M1 + l] = unpk2(acc2[t]);
    }
}

// ---------------------------------------------------------------------------
// Mode mix + gamma fold. W read coalesced from pre-transposed g_Wt[kl][p].
// ---------------------------------------------------------------------------
__global__ __launch_bounds__(256) void mixK() {
    __shared__ float2 Wsh[CI*CO];    // 32 KB
    __shared__ float2 Xsh[NB*CI];    //  8 KB
    int kl = blockIdx.x;
    int tid = threadIdx.x;
    const float4* wsrc = (const float4*)(g_Wt + (size_t)kl * 4096);
    for (int q = tid; q < 2048; q += 256)
        ((float4*)Wsh)[q] = wsrc[q];                  // coalesced 16B
    for (int p = tid; p < NB*CI; p += 256)
        Xsh[p] = ((const float2*)g_Xm)[(size_t)p*1024 + kl];
    __syncthreads();
#pragma unroll
    for (int q = 0; q < 4; q++) {
        int idx = tid + q*256;                        // b*64+o
        int b = idx >> 6, o = idx & 63;
        float yr = 0.f, yi = 0.f;
#pragma unroll 8
        for (int i = 0; i < CI; i++) {
            float2 xv = Xsh[(b << 6) + i];
            float2 wv = Wsh[(i << 6) + o];
            yr += xv.x*wv.x - xv.y*wv.y;
            yi += xv.x*wv.y + xv.y*wv.x;
        }
        float g = 1.0f + g_gamma[idx];
        ((float2*)g_Yb)[(size_t)idx*1024 + kl] = make_float2(g*yr, g*yi);
    }
}

// ---------------------------------------------------------------------------
// Stage C (f32x2, occupancy-fixed): grid NB*CO*4; block owns 64-h strip.
// ---------------------------------------------------------------------------
__global__ __launch_bounds__(256) void stageC() {
    __shared__ ulonglong2 twp[256];   // 4 KB
    __shared__ float2 Ysh[M0*M1];     // 8 KB
    int tid = threadIdx.x;
    { float s, c; sincosf(6.283185307179586f * (float)tid * (1.0f/256.0f), &s, &c);
      twp[tid] = make_ulonglong2(pack2(c, s), pack2(-s, c)); }
    int blk = blockIdx.x >> 2;                        // b*64+o
    int hq  = blockIdx.x & 3;
    const float2* Yp = (const float2*)g_Yb + (size_t)blk * (M0*M1);
    for (int p = tid; p < M0*M1; p += 256) Ysh[p] = Yp[p];
    __syncthreads();

    int l  = tid & 31;
    int h0 = (hq << 6) + (tid >> 5);                  // base h for this thread
    u64 acc2[8];
#pragma unroll
    for (int t = 0; t < 8; t++) acc2[t] = 0ULL;
    for (int k = 0; k < M0; k++) {
        float2 yv = Ysh[k*M1 + l];
        u64 yr2 = dup2(yv.x), yi2 = dup2(yv.y);
        int mm = (k * h0) & 255;
        int st = (k << 3) & 255;
#pragma unroll
        for (int t = 0; t < 8; t++) {
            ulonglong2 e = twp[mm];                   // warp-uniform broadcast
            fma2(acc2[t], e.x, yr2);
            fma2(acc2[t], e.y, yi2);
            mm = (mm + st) & 255;
        }
    }
    float2* Zp = (float2*)g_Z + (size_t)blk * HH * M1;
#pragma unroll
    for (int t = 0; t < 8; t++)
        Zp[(h0 + (t << 3))*M1 + l] = unpk2(acc2[t]);
}

// ---------------------------------------------------------------------------
// Fused inverse-w DFT + beta + bypass + GELU, 4-column w-mirror version.
// 64 threads; thread t serves columns {t, 256-t, t+128, 128-t} from four
// parity-split spectral sums (even/odd l), so spectral fma2 and ALL smem
// reads are shared 4 ways. Columns 64,192 (not covered by the group for
// t<64) are done cooperatively via their {0,+-1} cos/sin patterns.
// ---------------------------------------------------------------------------
__global__ __launch_bounds__(64) void specfinal6K(const float* __restrict__ x,
                                                  const float* __restrict__ bw,
                                                  const float* __restrict__ bb,
                                                  float* __restrict__ out) {
    __shared__ __align__(16) float zzRe[32*32];   // [l][o2] 4KB (norm folded)
    __shared__ __align__(16) float zzIm[32*32];   // [l][o2] 4KB
    __shared__ __align__(16) float bwt [64*32];   // [i][o2] 8KB
    __shared__ __align__(16) float xsp [128];     // x at w=64 (i<64), w=192
    __shared__ __align__(16) float beta_s[32];
    int t = threadIdx.x;                          // 0..63
    int b     = blockIdx.x >> 9;
    int h     = (blockIdx.x >> 1) & 255;
    int obase = (blockIdx.x & 1) << 5;            // 0 or 32

    size_t xrow = (size_t)b * CI * HH * WW + (size_t)h * WW;
    for (int p = t; p < 2048; p += 64) {
        int i = p >> 5, o2 = p & 31;
        bwt[p] = bw[(size_t)(obase + o2) * 64 + i];
    }
    const float nrm = 1.0f / 65536.0f;
    for (int p = t; p < 1024; p += 64) {
        int o2 = p >> 5, l = p & 31;
        float2 v = ((const float2*)g_Z)[((size_t)(b*64 + obase + o2) * 256 + h) * 32 + l];
        zzRe[l*32 + o2] = v.x * (l ? 2.0f*nrm : nrm);
        zzIm[l*32 + o2] = v.y * (-2.0f*nrm);
    }
    for (int p = t; p < 128; p += 64) {           // x columns 64 / 192
        int g = p >> 6, i = p & 63;
        xsp[p] = x[xrow + (size_t)i * HH * WW + 64 + (g << 7)];
    }
    if (t < 32) beta_s[t] = g_beta[b*64 + obase + t] + bb[obase + t];
    __syncthreads();

    // Four parity-split sums, 16 u64 (=32 o) each.
    u64 Ace[16], Aco[16], Ase[16], Aso[16];
#pragma unroll
    for (int p = 0; p < 16; p++) { Ace[p]=0ULL; Aco[p]=0ULL; Ase[p]=0ULL; Aso[p]=0ULL; }

    // Spectral: rotation recurrence at angle 2*pi*t/256.
    float cr, sr;
    sincosf(6.283185307179586f * (float)t * (1.0f/256.0f), &sr, &cr);
    float c = 1.0f, s = 0.0f;
#pragma unroll
    for (int l = 0; l < 32; l++) {
        u64 cd = dup2(c), sd = dup2(s);
        const ulonglong2* zr = (const ulonglong2*)(zzRe + l*32);
        const ulonglong2* zi = (const ulonglong2*)(zzIm + l*32);
        if ((l & 1) == 0) {
#pragma unroll
            for (int og = 0; og < 8; og++) {
                ulonglong2 zp = zr[og], ip = zi[og];      // broadcast LDS.128
                fma2(Ace[2*og], zp.x, cd); fma2(Ace[2*og+1], zp.y, cd);
                fma2(Ase[2*og], ip.x, sd); fma2(Ase[2*og+1], ip.y, sd);
            }
        } else {
#pragma unroll
            for (int og = 0; og < 8; og++) {
                ulonglong2 zp = zr[og], ip = zi[og];
                fma2(Aco[2*og], zp.x, cd); fma2(Aco[2*og+1], zp.y, cd);
                fma2(Aso[2*og], ip.x, sd); fma2(Aso[2*og+1], ip.y, sd);
            }
        }
        float cn = c*cr - s*sr;
        float sn = s*cr + c*sr;
        c = cn; s = sn;
    }

    // Combine in place:
    //  Ace -> col w      = (Sce+Sco)+(Sse+Sso)
    //  Aco -> col 256-w  = (Sce+Sco)-(Sse+Sso)
    //  Ase -> col w+128  = (Sce-Sco)+(Sse-Sso)
    //  Aso -> col 128-w  = (Sce-Sco)-(Sse-Sso)
#pragma unroll
    for (int p = 0; p < 16; p++) {
        u64 P = add2(Ace[p], Aco[p]);
        u64 M = sub2(Ace[p], Aco[p]);
        u64 Q = add2(Ase[p], Aso[p]);
        u64 R = sub2(Ase[p], Aso[p]);
        Ace[p] = add2(P, Q);
        Aco[p] = sub2(P, Q);
        Ase[p] = add2(M, R);
        Aso[p] = sub2(M, R);
    }

    // Column indices (t=0 degeneracies collapse to same-thread duplicate
    // writes of identical values — benign).
    int wA = t, wB = (256 - t) & 255, wC = 128 + t, wD = 128 - t;
    const float* xp = x + xrow;

    // Bypass: each bwt row feeds all 4 columns. 2-deep channel pipeline.
    float cur[4], nxt[4];
    cur[0] = xp[wA]; cur[1] = xp[wB]; cur[2] = xp[wC]; cur[3] = xp[wD];
    for (int i = 0; i < CI; i++) {
        if (i + 1 < CI) {
            size_t off = (size_t)(i + 1) * HH * WW;
            nxt[0] = xp[off + wA]; nxt[1] = xp[off + wB];
            nxt[2] = xp[off + wC]; nxt[3] = xp[off + wD];
        }
        u64 xA = dup2(cur[0]), xB = dup2(cur[1]);
        u64 xC = dup2(cur[2]), xD = dup2(cur[3]);
        const ulonglong2* wr2 = (const ulonglong2*)(bwt + (i << 5));
#pragma unroll
        for (int og = 0; og < 8; og++) {
            ulonglong2 wp = wr2[og];                  // broadcast LDS.128
            fma2(Ace[2*og], wp.x, xA); fma2(Ace[2*og+1], wp.y, xA);
            fma2(Aco[2*og], wp.x, xB); fma2(Aco[2*og+1], wp.y, xB);
            fma2(Ase[2*og], wp.x, xC); fma2(Ase[2*og+1], wp.y, xC);
            fma2(Aso[2*og], wp.x, xD); fma2(Aso[2*og+1], wp.y, xD);
        }
#pragma unroll
        for (int j = 0; j < 4; j++) cur[j] = nxt[j];
    }

    size_t ob = (size_t)b * CO * HH * WW + (size_t)obase * HH * WW
              + (size_t)h * WW;
#pragma unroll 4
    for (int p = 0; p < 16; p++) {
        u64 bp = *(const u64*)&beta_s[p << 1];
        float2 vA = unpk2(add2(Ace[p], bp));
        float2 vB = unpk2(add2(Aco[p], bp));
        float2 vC = unpk2(add2(Ase[p], bp));
        float2 vD = unpk2(add2(Aso[p], bp));
        size_t r0 = ob + (size_t)(2*p    ) * HH * WW;
        size_t r1 = ob + (size_t)(2*p + 1) * HH * WW;
        out[r0 + wA] = gelu_tanh(vA.x);  out[r1 + wA] = gelu_tanh(vA.y);
        out[r0 + wB] = gelu_tanh(vB.x);  out[r1 + wB] = gelu_tanh(vB.y);
        out[r0 + wC] = gelu_tanh(vC.x);  out[r1 + wC] = gelu_tanh(vC.y);
        out[r0 + wD] = gelu_tanh(vD.x);  out[r1 + wD] = gelu_tanh(vD.y);
    }

    // Special columns w = 64 (grp 0) and w = 192 (grp 1):
    // cos(pi*l/2) pattern {1,0,-1,0}; sin(+/-pi*l/2) = {0,+/-1,0,-/+1}.
    {
        int grp = t >> 5, o2 = t & 31;
        float sgn = grp ? -1.0f : 1.0f;
        float sre = 0.0f, sim = 0.0f;
#pragma unroll
        for (int m = 0; m < 8; m++) {
            sre += zzRe[(4*m    )*32 + o2] - zzRe[(4*m + 2)*32 + o2];
            sim += zzIm[(4*m + 1)*32 + o2] - zzIm[(4*m + 3)*32 + o2];
        }
        float val = sre + sgn * sim;
        float b0 = 0.f, b1v = 0.f, b2v = 0.f, b3 = 0.f;
#pragma unroll 4
        for (int i = 0; i < CI; i += 4) {
            b0  = fmaf(bwt[(i  )*32 + o2], xsp[(grp<<6) + i    ], b0);
            b1v = fmaf(bwt[(i+1)*32 + o2], xsp[(grp<<6) + i + 1], b1v);
            b2v = fmaf(bwt[(i+2)*32 + o2], xsp[(grp<<6) + i + 2], b2v);
            b3  = fmaf(bwt[(i+3)*32 + o2], xsp[(grp<<6) + i + 3], b3);
        }
        val += (b0 + b1v) + (b2v + b3) + beta_s[o2];
        int wsp = 64 + (grp << 7);
        out[ob + (size_t)o2 * HH * WW + wsp] = gelu_tanh(val);
    }
}

// ---------------------------------------------------------------------------
extern "C" void kernel_launch(void* const* d_in, const int* in_sizes, int n_in,
                              void* d_out, int out_size) {
    const float* x      = (const float*)d_in[0];
    const float* t_emb  = (const float*)d_in[1];
    const float* w_real = (const float*)d_in[2];
    const float* w_imag = (const float*)d_in[3];
    const float* fw1    = (const float*)d_in[4];
    const float* fb1    = (const float*)d_in[5];
    const float* fw2    = (const float*)d_in[6];
    const float* fb2    = (const float*)d_in[7];
    const float* bw     = (const float*)d_in[8];
    const float* bb     = (const float*)d_in[9];
    float* out = (float*)d_out;

    const int smemA = A3_SMEM * sizeof(float);                        // 102536
    cudaFuncSetAttribute(stageA5, cudaFuncAttributeMaxDynamicSharedMemorySize, smemA);

    stageA5<<<4097, 256, smemA>>>(x, w_real, w_imag, t_emb,
                                  fw1, fb1, fw2, fb2);                // 1
    stageB<<<NB*CI, 256>>>();                                         // 2
    mixK<<<M0*M1, 256>>>();                                           // 3
    stageC<<<NB*CO*4, 256>>>();                                       // 4 <- profiled
    specfinal6K<<<NB*HH*2, 64>>>(x, bw, bb, out);                     // 5
}

// round 16
// speedup vs baseline: 1.9030x; 1.9030x over previous
#include <cuda_runtime.h>
#include <math.h>

// Shapes (fixed for this problem)
#define NB 16
#define CI 64
#define CO 64
#define HH 256
#define WW 256
#define M0 32
#define M1 32

typedef unsigned long long u64;

// Scratch (device globals; no allocation allowed in kernel_launch)
__device__ __align__(256) float g_Xw [(size_t)NB*CI*HH*M1*2]; // 67 MB  [b][i][h][l]{re,im}
__device__ __align__(256) float g_Xm [(size_t)NB*CI*M0*M1*2]; // 8.4 MB [b][i][k*32+l]{re,im}
__device__ __align__(256) float g_Yb [(size_t)NB*CO*M0*M1*2]; // 8.4 MB [b][o][k*32+l]{re,im}
__device__ __align__(256) float g_Z  [(size_t)NB*CO*HH*M1*2]; // 67 MB  [b][o][h][l]{re,im}
__device__ __align__(256) float2 g_Wt[(size_t)M0*M1*CI*CO];   // 33.5MB [kl][i*64+o]{re,im}
__device__ __align__(256) float g_gamma[NB*CO];
__device__ __align__(256) float g_beta [NB*CO];

// ---- packed fp32x2 helpers (SASS FFMA2 path; PTX-only, ptxas won't emit) ----
__device__ __forceinline__ u64 pack2(float lo, float hi) {
    u64 r; asm("mov.b64 %0, {%1, %2};" : "=l"(r) : "f"(lo), "f"(hi)); return r;
}
__device__ __forceinline__ u64 dup2(float v) { return pack2(v, v); }
__device__ __forceinline__ void fma2(u64 &d, u64 a, u64 b) {
    asm("fma.rn.f32x2 %0, %1, %2, %0;" : "+l"(d) : "l"(a), "l"(b));
}
__device__ __forceinline__ u64 add2(u64 a, u64 b) {
    u64 r; asm("add.rn.f32x2 %0, %1, %2;" : "=l"(r) : "l"(a), "l"(b)); return r;
}
__device__ __forceinline__ u64 sub2(u64 a, u64 b) {
    u64 r; asm("sub.rn.f32x2 %0, %1, %2;" : "=l"(r) : "l"(a), "l"(b)); return r;
}
__device__ __forceinline__ float2 unpk2(u64 v) {
    float2 f; asm("mov.b64 {%0, %1}, %2;" : "=f"(f.x), "=f"(f.y) : "l"(v)); return f;
}

__device__ __forceinline__ float gelu_tanh(float x) {
    float u = 0.7978845608028654f * (x + 0.044715f * x * x * x);
    float t;
    asm("tanh.approx.f32 %0, %1;" : "=f"(t) : "f"(u));
    return 0.5f * x * (1.0f + t);
}

// ---------------------------------------------------------------------------
// Stage A (merged with setup): grid 4097. f32x2 accumulation over l-pairs.
// ---------------------------------------------------------------------------
#define A3_U   0
#define A3_V   8448      // 64*132
#define A3_TC  16896
#define A3_TS  21282     // 16896 + 129*34
#define A3_SMEM (21282 + 128*34)   // 25634 floats

__global__ __launch_bounds__(256) void stageA5(const float* __restrict__ x,
                                               const float* __restrict__ wr,
                                               const float* __restrict__ wi,
                                               const float* __restrict__ t_emb,
                                               const float* __restrict__ w1,
                                               const float* __restrict__ b1,
                                               const float* __restrict__ w2,
                                               const float* __restrict__ b2) {
    extern __shared__ float sm[];
    int tid = threadIdx.x;
    int bid = blockIdx.x;
    const float TWO_PI = 6.283185307179586f;

    if (bid >= 4096) {                    // ---- FiLM block ----
        float* tsh = sm;
        float* hsh = sm + 1024;
        for (int p = tid; p < NB*CI; p += 256) tsh[p] = t_emb[p];
        __syncthreads();
        for (int p = tid; p < NB*CI; p += 256) {
            int b = p >> 6, j = p & 63;
            float s = b1[j];
            for (int i = 0; i < CI; i++) s += tsh[(b<<6)+i] * w1[i*CI + j];
            hsh[p] = s / (1.0f + expf(-s));
        }
        __syncthreads();
        for (int p = tid; p < NB*2*CO; p += 256) {
            int b = p >> 7, j = p & 127;
            float s = b2[j];
            for (int i = 0; i < CI; i++) s += hsh[(b<<6)+i] * w2[i*(2*CO) + j];
            if (j < CO) g_gamma[(b<<6)+j] = s;
            else        g_beta [(b<<6)+j-CO] = s;
        }
        return;
    }

    // ---- W-transpose side-task ----
    {
        int p0  = (bid >> 5) << 5;
        int kl0 = (bid & 31) << 5;
        for (int q = tid; q < 1024; q += 256) {
            int r = q >> 5, c = q & 31;
            float a  = wr[(size_t)(p0 + r) * 1024 + kl0 + c];
            float bv = wi[(size_t)(p0 + r) * 1024 + kl0 + c];
            g_Wt[(size_t)(kl0 + c) * 4096 + p0 + r] = make_float2(a, bv);
        }
    }

    // ---- Stage A proper ----
    float* U  = sm + A3_U;
    float* V  = sm + A3_V;
    float* Tc = sm + A3_TC;
    float* Ts = sm + A3_TS;
    int lane = tid & 31, wid = tid >> 5;
    int b = bid >> 8;
    int h = bid & 255;

    for (int p = tid; p < 129*32; p += 256) {     // tables inline, exact phase
        int w = p >> 5, l = p & 31;
        int m = (w * l) & 255;
        float s, c; sincosf(TWO_PI * (float)m * (1.0f/256.0f), &s, &c);
        Tc[w*34 + l] = c;
        if (w < 128) Ts[w*34 + l] = -s;
    }

    size_t xbase = (size_t)b * CI * HH * WW + (size_t)h * WW;
    for (int i = wid; i < 64; i += 8) {
        const float4* xr = (const float4*)(x + xbase + (size_t)i * HH * WW);
        float4 A4 = xr[lane];
        float4 B4 = xr[63 - lane];
        float m0 = __shfl_up_sync(0xffffffffu, B4.x, 1);
        float4 u, v;
        if (lane == 0) { u.x = A4.x;      v.x = 0.0f; }
        else           { u.x = A4.x + m0; v.x = A4.x - m0; }
        u.y = A4.y + B4.w;  v.y = A4.y - B4.w;
        u.z = A4.z + B4.z;  v.z = A4.z - B4.z;
        u.w = A4.w + B4.y;  v.w = A4.w - B4.y;
        *(float4*)&U[i*132 + 4*lane] = u;
        *(float4*)&V[i*132 + 4*lane] = v;
        if (lane == 31) U[i*132 + 128] = B4.x;
    }
    __syncthreads();

    int i0 = (tid >> 4) << 2;
    int l0 = (tid & 15) << 1;
    u64 re2[4], im2[4];
#pragma unroll
    for (int r = 0; r < 4; r++) { re2[r] = 0ULL; im2[r] = 0ULL; }

    const float* U0  = U + i0*132;
    const float* V0  = V + i0*132;
    const float* Tcp = Tc + l0;
    const float* Tsp = Ts + l0;
#pragma unroll 3
    for (int w = 0; w < 129; w++) {
        u64 cd = *(const u64*)&Tcp[w*34];            // packed (cos_l0, cos_l0+1)
        fma2(re2[0], cd, dup2(U0[w]));
        fma2(re2[1], cd, dup2(U0[132+w]));
        fma2(re2[2], cd, dup2(U0[264+w]));
        fma2(re2[3], cd, dup2(U0[396+w]));
    }
#pragma unroll 4
    for (int w = 0; w < 128; w++) {
        u64 sd = *(const u64*)&Tsp[w*34];            // packed (-sin_l0, -sin_l0+1)
        fma2(im2[0], sd, dup2(V0[w]));
        fma2(im2[1], sd, dup2(V0[132+w]));
        fma2(im2[2], sd, dup2(V0[264+w]));
        fma2(im2[3], sd, dup2(V0[396+w]));
    }
#pragma unroll
    for (int r = 0; r < 4; r++) {
        float2 rr = unpk2(re2[r]);
        float2 mm = unpk2(im2[r]);
        size_t idx = (((size_t)(b*64 + i0 + r) * 256 + h) * 64) + 2*l0;
        *(float4*)&g_Xw[idx] = make_float4(rr.x, mm.x, rr.y, mm.y);
    }
}

// ---------------------------------------------------------------------------
// Stage B (f32x2 + h-parity fold).
// ---------------------------------------------------------------------------
__global__ __launch_bounds__(256) void stageB() {
    __shared__ ulonglong2 twp[256];   // 4 KB
    int tid = threadIdx.x;
    { float s, c; sincosf(6.283185307179586f * (float)tid * (1.0f/256.0f), &s, &c);
      twp[tid] = make_ulonglong2(pack2(c, -s), pack2(s, c)); }
    __syncthreads();
    int blk = blockIdx.x;                             // b*64+i
    const float2* Xp = (const float2*)(g_Xw) + (size_t)blk * HH * M1;
    int l  = tid & 31;
    int k0 = tid >> 5;
    float sg = (k0 & 1) ? -1.0f : 1.0f;               // (-1)^k, warp-uniform
    u64 acc2[4];
    int mt[4];
#pragma unroll
    for (int t = 0; t < 4; t++) { acc2[t] = 0ULL; mt[t] = 0; }
    for (int h = 0; h < 128; h++) {
        float2 xa = Xp[h*M1 + l];
        float2 xb = Xp[(h+128)*M1 + l];
        u64 zr2 = dup2(fmaf(sg, xb.x, xa.x));
        u64 zi2 = dup2(fmaf(sg, xb.y, xa.y));
#pragma unroll
        for (int t = 0; t < 4; t++) {
            ulonglong2 e = twp[mt[t]];                // broadcast LDS.128
            fma2(acc2[t], e.x, zr2);
            fma2(acc2[t], e.y, zi2);
            mt[t] = (mt[t] + k0 + (t << 3)) & 255;
        }
    }
    float2* Om = (float2*)g_Xm + (size_t)blk * (M0*M1);
#pragma unroll
    for (int t = 0; t < 4; t++) {
        int k = k0 + (t << 3);
        Om[k*M1 + l] = unpk2(acc2[t]);
    }
}

// ---------------------------------------------------------------------------
// Mode mix + gamma fold. W read coalesced from pre-transposed g_Wt[kl][p].
// ---------------------------------------------------------------------------
__global__ __launch_bounds__(256) void mixK() {
    __shared__ float2 Wsh[CI*CO];    // 32 KB
    __shared__ float2 Xsh[NB*CI];    //  8 KB
    int kl = blockIdx.x;
    int tid = threadIdx.x;
    const float4* wsrc = (const float4*)(g_Wt + (size_t)kl * 4096);
    for (int q = tid; q < 2048; q += 256)
        ((float4*)Wsh)[q] = wsrc[q];                  // coalesced 16B
    for (int p = tid; p < NB*CI; p += 256)
        Xsh[p] = ((const float2*)g_Xm)[(size_t)p*1024 + kl];
    __syncthreads();
#pragma unroll
    for (int q = 0; q < 4; q++) {
        int idx = tid + q*256;                        // b*64+o
        int b = idx >> 6, o = idx & 63;
        float yr = 0.f, yi = 0.f;
#pragma unroll 8
        for (int i = 0; i < CI; i++) {
            float2 xv = Xsh[(b << 6) + i];
            float2 wv = Wsh[(i << 6) + o];
            yr += xv.x*wv.x - xv.y*wv.y;
            yi += xv.x*wv.y + xv.y*wv.x;
        }
        float g = 1.0f + g_gamma[idx];
        ((float2*)g_Yb)[(size_t)idx*1024 + kl] = make_float2(g*yr, g*yi);
    }
}

// ---------------------------------------------------------------------------
// Stage C (f32x2, occupancy-fixed): grid NB*CO*4; block owns 64-h strip.
// ---------------------------------------------------------------------------
__global__ __launch_bounds__(256) void stageC() {
    __shared__ ulonglong2 twp[256];   // 4 KB
    __shared__ float2 Ysh[M0*M1];     // 8 KB
    int tid = threadIdx.x;
    { float s, c; sincosf(6.283185307179586f * (float)tid * (1.0f/256.0f), &s, &c);
      twp[tid] = make_ulonglong2(pack2(c, s), pack2(-s, c)); }
    int blk = blockIdx.x >> 2;                        // b*64+o
    int hq  = blockIdx.x & 3;
    const float2* Yp = (const float2*)g_Yb + (size_t)blk * (M0*M1);
    for (int p = tid; p < M0*M1; p += 256) Ysh[p] = Yp[p];
    __syncthreads();

    int l  = tid & 31;
    int h0 = (hq << 6) + (tid >> 5);                  // base h for this thread
    u64 acc2[8];
#pragma unroll
    for (int t = 0; t < 8; t++) acc2[t] = 0ULL;
    for (int k = 0; k < M0; k++) {
        float2 yv = Ysh[k*M1 + l];
        u64 yr2 = dup2(yv.x), yi2 = dup2(yv.y);
        int mm = (k * h0) & 255;
        int st = (k << 3) & 255;
#pragma unroll
        for (int t = 0; t < 8; t++) {
            ulonglong2 e = twp[mm];                   // warp-uniform broadcast
            fma2(acc2[t], e.x, yr2);
            fma2(acc2[t], e.y, yi2);
            mm = (mm + st) & 255;
        }
    }
    float2* Zp = (float2*)g_Z + (size_t)blk * HH * M1;
#pragma unroll
    for (int t = 0; t < 8; t++)
        Zp[(h0 + (t << 3))*M1 + l] = unpk2(acc2[t]);
}

// ---------------------------------------------------------------------------
// Fused inverse-w DFT + beta + bypass + GELU: 4-column w-mirror x 16-o split.
// Block = (b, h, o-quarter); 64 threads. Thread t serves columns
// {t, 256-t, 128+t, 128-t} for 16 o. Accumulators: 4 groups x 8 u64 = 64
// regs (the proven specfinal5K budget -> no spill). Spectral flops 4x-shared,
// bw rows 4x-shared. Missing columns {64,192} handled cooperatively.
// ---------------------------------------------------------------------------
__global__ __launch_bounds__(64) void specfinal7K(const float* __restrict__ x,
                                                  const float* __restrict__ bw,
                                                  const float* __restrict__ bb,
                                                  float* __restrict__ out) {
    __shared__ __align__(16) float zzRe[32*16];   // [l][o2] 2KB (norm folded)
    __shared__ __align__(16) float zzIm[32*16];   // [l][o2] 2KB
    __shared__ __align__(16) float bwt [64*16];   // [i][o2] 4KB
    __shared__ __align__(16) float xsp [128];     // x at w=64 (i<64), w=192
    __shared__ __align__(16) float beta_s[16];
    int t = threadIdx.x;                          // 0..63
    int b     = blockIdx.x >> 10;
    int h     = (blockIdx.x >> 2) & 255;
    int obase = (blockIdx.x & 3) << 4;            // 0,16,32,48

    size_t xrow = (size_t)b * CI * HH * WW + (size_t)h * WW;
    for (int p = t; p < 1024; p += 64) {
        int i = p >> 4, o2 = p & 15;
        bwt[p] = bw[(size_t)(obase + o2) * 64 + i];
    }
    const float nrm = 1.0f / 65536.0f;
    for (int p = t; p < 512; p += 64) {
        int o2 = p >> 5, l = p & 31;
        float2 v = ((const float2*)g_Z)[((size_t)(b*64 + obase + o2) * 256 + h) * 32 + l];
        zzRe[l*16 + o2] = v.x * (l ? 2.0f*nrm : nrm);
        zzIm[l*16 + o2] = v.y * (-2.0f*nrm);
    }
    for (int p = t; p < 128; p += 64) {           // x columns 64 / 192
        int g = p >> 6, i = p & 63;
        xsp[p] = x[xrow + (size_t)i * HH * WW + 64 + (g << 7)];
    }
    if (t < 16) beta_s[t] = g_beta[b*64 + obase + t] + bb[obase + t];
    __syncthreads();

    // Four parity-split sums, 8 u64 (=16 o) each -> 64 regs total.
    u64 Ace[8], Aco[8], Ase[8], Aso[8];
#pragma unroll
    for (int p = 0; p < 8; p++) { Ace[p]=0ULL; Aco[p]=0ULL; Ase[p]=0ULL; Aso[p]=0ULL; }

    // Spectral: rotation recurrence at angle 2*pi*t/256.
    float cr, sr;
    sincosf(6.283185307179586f * (float)t * (1.0f/256.0f), &sr, &cr);
    float c = 1.0f, s = 0.0f;
#pragma unroll
    for (int l = 0; l < 32; l++) {
        u64 cd = dup2(c), sd = dup2(s);
        const ulonglong2* zr = (const ulonglong2*)(zzRe + l*16);
        const ulonglong2* zi = (const ulonglong2*)(zzIm + l*16);
        if ((l & 1) == 0) {
#pragma unroll
            for (int og = 0; og < 4; og++) {
                ulonglong2 zp = zr[og], ip = zi[og];      // broadcast LDS.128
                fma2(Ace[2*og], zp.x, cd); fma2(Ace[2*og+1], zp.y, cd);
                fma2(Ase[2*og], ip.x, sd); fma2(Ase[2*og+1], ip.y, sd);
            }
        } else {
#pragma unroll
            for (int og = 0; og < 4; og++) {
                ulonglong2 zp = zr[og], ip = zi[og];
                fma2(Aco[2*og], zp.x, cd); fma2(Aco[2*og+1], zp.y, cd);
                fma2(Aso[2*og], ip.x, sd); fma2(Aso[2*og+1], ip.y, sd);
            }
        }
        float cn = c*cr - s*sr;
        float sn = s*cr + c*sr;
        c = cn; s = sn;
    }

    // Combine in place:
    //  Ace -> col w      = (Sce+Sco)+(Sse+Sso)
    //  Aco -> col 256-w  = (Sce+Sco)-(Sse+Sso)
    //  Ase -> col w+128  = (Sce-Sco)+(Sse-Sso)
    //  Aso -> col 128-w  = (Sce-Sco)-(Sse-Sso)
#pragma unroll
    for (int p = 0; p < 8; p++) {
        u64 P = add2(Ace[p], Aco[p]);
        u64 M = sub2(Ace[p], Aco[p]);
        u64 Q = add2(Ase[p], Aso[p]);
        u64 R = sub2(Ase[p], Aso[p]);
        Ace[p] = add2(P, Q);
        Aco[p] = sub2(P, Q);
        Ase[p] = add2(M, R);
        Aso[p] = sub2(M, R);
    }

    // Column indices (t=0 degeneracies: duplicate same-value writes, benign).
    int wA = t, wB = (256 - t) & 255, wC = 128 + t, wD = 128 - t;
    const float* xp = x + xrow;

    // Bypass: each bwt row feeds all 4 columns. 2-deep channel pipeline.
    float cur[4], nxt[4];
    cur[0] = xp[wA]; cur[1] = xp[wB]; cur[2] = xp[wC]; cur[3] = xp[wD];
    for (int i = 0; i < CI; i++) {
        if (i + 1 < CI) {
            size_t off = (size_t)(i + 1) * HH * WW;
            nxt[0] = xp[off + wA]; nxt[1] = xp[off + wB];
            nxt[2] = xp[off + wC]; nxt[3] = xp[off + wD];
        }
        u64 xA = dup2(cur[0]), xB = dup2(cur[1]);
        u64 xC = dup2(cur[2]), xD = dup2(cur[3]);
        const ulonglong2* wr2 = (const ulonglong2*)(bwt + (i << 4));
#pragma unroll
        for (int og = 0; og < 4; og++) {
            ulonglong2 wp = wr2[og];                  // broadcast LDS.128
            fma2(Ace[2*og], wp.x, xA); fma2(Ace[2*og+1], wp.y, xA);
            fma2(Aco[2*og], wp.x, xB); fma2(Aco[2*og+1], wp.y, xB);
            fma2(Ase[2*og], wp.x, xC); fma2(Ase[2*og+1], wp.y, xC);
            fma2(Aso[2*og], wp.x, xD); fma2(Aso[2*og+1], wp.y, xD);
        }
#pragma unroll
        for (int j = 0; j < 4; j++) cur[j] = nxt[j];
    }

    size_t ob = (size_t)b * CO * HH * WW + (size_t)obase * HH * WW
              + (size_t)h * WW;
#pragma unroll 4
    for (int p = 0; p < 8; p++) {
        u64 bp = *(const u64*)&beta_s[p << 1];
        float2 vA = unpk2(add2(Ace[p], bp));
        float2 vB = unpk2(add2(Aco[p], bp));
        float2 vC = unpk2(add2(Ase[p], bp));
        float2 vD = unpk2(add2(Aso[p], bp));
        size_t r0 = ob + (size_t)(2*p    ) * HH * WW;
        size_t r1 = ob + (size_t)(2*p + 1) * HH * WW;
        out[r0 + wA] = gelu_tanh(vA.x);  out[r1 + wA] = gelu_tanh(vA.y);
        out[r0 + wB] = gelu_tanh(vB.x);  out[r1 + wB] = gelu_tanh(vB.y);
        out[r0 + wC] = gelu_tanh(vC.x);  out[r1 + wC] = gelu_tanh(vC.y);
        out[r0 + wD] = gelu_tanh(vD.x);  out[r1 + wD] = gelu_tanh(vD.y);
    }

    // Special columns w = 64 (grp 0) and w = 192 (grp 1): 2 cols x 16 o.
    // cos(pi*l/2) in {1,0,-1,0}; sin(+/-pi*l/2) in {0,+/-1,0,-/+1}.
    if (t < 32) {
        int grp = t >> 4, o2 = t & 15;
        float sgn = grp ? -1.0f : 1.0f;
        float sre = 0.0f, sim = 0.0f;
#pragma unroll
        for (int m = 0; m < 8; m++) {
            sre += zzRe[(4*m    )*16 + o2] - zzRe[(4*m + 2)*16 + o2];
            sim += zzIm[(4*m + 1)*16 + o2] - zzIm[(4*m + 3)*16 + o2];
        }
        float val = sre + sgn * sim;
        float b0 = 0.f, b1v = 0.f, b2v = 0.f, b3 = 0.f;
#pragma unroll 4
        for (int i = 0; i < CI; i += 4) {
            b0  = fmaf(bwt[(i  )*16 + o2], xsp[(grp<<6) + i    ], b0);
            b1v = fmaf(bwt[(i+1)*16 + o2], xsp[(grp<<6) + i + 1], b1v);
            b2v = fmaf(bwt[(i+2)*16 + o2], xsp[(grp<<6) + i + 2], b2v);
            b3  = fmaf(bwt[(i+3)*16 + o2], xsp[(grp<<6) + i + 3], b3);
        }
        val += (b0 + b1v) + (b2v + b3) + beta_s[o2];
        int wsp = 64 + (grp << 7);
        out[ob + (size_t)o2 * HH * WW + wsp] = gelu_tanh(val);
    }
}

// ---------------------------------------------------------------------------
extern "C" void kernel_launch(void* const* d_in, const int* in_sizes, int n_in,
                              void* d_out, int out_size) {
    const float* x      = (const float*)d_in[0];
    const float* t_emb  = (const float*)d_in[1];
    const float* w_real = (const float*)d_in[2];
    const float* w_imag = (const float*)d_in[3];
    const float* fw1    = (const float*)d_in[4];
    const float* fb1    = (const float*)d_in[5];
    const float* fw2    = (const float*)d_in[6];
    const float* fb2    = (const float*)d_in[7];
    const float* bw     = (const float*)d_in[8];
    const float* bb     = (const float*)d_in[9];
    float* out = (float*)d_out;

    const int smemA = A3_SMEM * sizeof(float);                        // 102536
    cudaFuncSetAttribute(stageA5, cudaFuncAttributeMaxDynamicSharedMemorySize, smemA);

    stageA5<<<4097, 256, smemA>>>(x, w_real, w_imag, t_emb,
                                  fw1, fb1, fw2, fb2);                // 1
    stageB<<<NB*CI, 256>>>();                                         // 2
    mixK<<<M0*M1, 256>>>();                                           // 3
    stageC<<<NB*CO*4, 256>>>();                                       // 4 <- profiled
    specfinal7K<<<NB*HH*4, 64>>>(x, bw, bb, out);                     // 5
}

// round 17
// speedup vs baseline: 1.9558x; 1.0278x over previous
#include <cuda_runtime.h>
#include <math.h>

// Shapes (fixed for this problem)
#define NB 16
#define CI 64
#define CO 64
#define HH 256
#define WW 256
#define M0 32
#define M1 32

typedef unsigned long long u64;

// Scratch (device globals; no allocation allowed in kernel_launch)
__device__ __align__(256) float g_Xw [(size_t)NB*CI*HH*M1*2]; // 67 MB  [b][i][h][l]{re,im}
__device__ __align__(256) float g_Xm [(size_t)NB*CI*M0*M1*2]; // 8.4 MB [b][i][k*32+l]{re,im}
__device__ __align__(256) float g_Yb [(size_t)NB*CO*M0*M1*2]; // 8.4 MB [b][o][k*32+l]{re,im}
__device__ __align__(256) float g_Z  [(size_t)NB*CO*HH*M1*2]; // 67 MB  [b][o][h][l]{re,im}
__device__ __align__(256) float2 g_Wt[(size_t)M0*M1*CI*CO];   // 33.5MB [kl][i*64+o]{re,im}
__device__ __align__(256) float g_gamma[NB*CO];
__device__ __align__(256) float g_beta [NB*CO];

// ---- packed fp32x2 helpers (SASS FFMA2 path; PTX-only, ptxas won't emit) ----
__device__ __forceinline__ u64 pack2(float lo, float hi) {
    u64 r; asm("mov.b64 %0, {%1, %2};" : "=l"(r) : "f"(lo), "f"(hi)); return r;
}
__device__ __forceinline__ u64 dup2(float v) { return pack2(v, v); }
__device__ __forceinline__ void fma2(u64 &d, u64 a, u64 b) {
    asm("fma.rn.f32x2 %0, %1, %2, %0;" : "+l"(d) : "l"(a), "l"(b));
}
__device__ __forceinline__ u64 add2(u64 a, u64 b) {
    u64 r; asm("add.rn.f32x2 %0, %1, %2;" : "=l"(r) : "l"(a), "l"(b)); return r;
}
__device__ __forceinline__ u64 sub2(u64 a, u64 b) {
    u64 r; asm("sub.rn.f32x2 %0, %1, %2;" : "=l"(r) : "l"(a), "l"(b)); return r;
}
__device__ __forceinline__ float2 unpk2(u64 v) {
    float2 f; asm("mov.b64 {%0, %1}, %2;" : "=f"(f.x), "=f"(f.y) : "l"(v)); return f;
}

__device__ __forceinline__ float gelu_tanh(float x) {
    float u = 0.7978845608028654f * (x + 0.044715f * x * x * x);
    float t;
    asm("tanh.approx.f32 %0, %1;" : "=f"(t) : "f"(u));
    return 0.5f * x * (1.0f + t);
}

// ---------------------------------------------------------------------------
// Stage A (merged with setup): grid 4097. f32x2 accumulation over l-pairs.
// ---------------------------------------------------------------------------
#define A3_U   0
#define A3_V   8448      // 64*132
#define A3_TC  16896
#define A3_TS  21282     // 16896 + 129*34
#define A3_SMEM (21282 + 128*34)   // 25634 floats

__global__ __launch_bounds__(256) void stageA5(const float* __restrict__ x,
                                               const float* __restrict__ wr,
                                               const float* __restrict__ wi,
                                               const float* __restrict__ t_emb,
                                               const float* __restrict__ w1,
                                               const float* __restrict__ b1,
                                               const float* __restrict__ w2,
                                               const float* __restrict__ b2) {
    extern __shared__ float sm[];
    int tid = threadIdx.x;
    int bid = blockIdx.x;
    const float TWO_PI = 6.283185307179586f;

    if (bid >= 4096) {                    // ---- FiLM block ----
        float* tsh = sm;
        float* hsh = sm + 1024;
        for (int p = tid; p < NB*CI; p += 256) tsh[p] = t_emb[p];
        __syncthreads();
        for (int p = tid; p < NB*CI; p += 256) {
            int b = p >> 6, j = p & 63;
            float s = b1[j];
            for (int i = 0; i < CI; i++) s += tsh[(b<<6)+i] * w1[i*CI + j];
            hsh[p] = s / (1.0f + expf(-s));
        }
        __syncthreads();
        for (int p = tid; p < NB*2*CO; p += 256) {
            int b = p >> 7, j = p & 127;
            float s = b2[j];
            for (int i = 0; i < CI; i++) s += hsh[(b<<6)+i] * w2[i*(2*CO) + j];
            if (j < CO) g_gamma[(b<<6)+j] = s;
            else        g_beta [(b<<6)+j-CO] = s;
        }
        return;
    }

    // ---- W-transpose side-task ----
    {
        int p0  = (bid >> 5) << 5;
        int kl0 = (bid & 31) << 5;
        for (int q = tid; q < 1024; q += 256) {
            int r = q >> 5, c = q & 31;
            float a  = wr[(size_t)(p0 + r) * 1024 + kl0 + c];
            float bv = wi[(size_t)(p0 + r) * 1024 + kl0 + c];
            g_Wt[(size_t)(kl0 + c) * 4096 + p0 + r] = make_float2(a, bv);
        }
    }

    // ---- Stage A proper ----
    float* U  = sm + A3_U;
    float* V  = sm + A3_V;
    float* Tc = sm + A3_TC;
    float* Ts = sm + A3_TS;
    int lane = tid & 31, wid = tid >> 5;
    int b = bid >> 8;
    int h = bid & 255;

    for (int p = tid; p < 129*32; p += 256) {     // tables inline, exact phase
        int w = p >> 5, l = p & 31;
        int m = (w * l) & 255;
        float s, c; sincosf(TWO_PI * (float)m * (1.0f/256.0f), &s, &c);
        Tc[w*34 + l] = c;
        if (w < 128) Ts[w*34 + l] = -s;
    }

    size_t xbase = (size_t)b * CI * HH * WW + (size_t)h * WW;
    for (int i = wid; i < 64; i += 8) {
        const float4* xr = (const float4*)(x + xbase + (size_t)i * HH * WW);
        float4 A4 = xr[lane];
        float4 B4 = xr[63 - lane];
        float m0 = __shfl_up_sync(0xffffffffu, B4.x, 1);
        float4 u, v;
        if (lane == 0) { u.x = A4.x;      v.x = 0.0f; }
        else           { u.x = A4.x + m0; v.x = A4.x - m0; }
        u.y = A4.y + B4.w;  v.y = A4.y - B4.w;
        u.z = A4.z + B4.z;  v.z = A4.z - B4.z;
        u.w = A4.w + B4.y;  v.w = A4.w - B4.y;
        *(float4*)&U[i*132 + 4*lane] = u;
        *(float4*)&V[i*132 + 4*lane] = v;
        if (lane == 31) U[i*132 + 128] = B4.x;
    }
    __syncthreads();

    int i0 = (tid >> 4) << 2;
    int l0 = (tid & 15) << 1;
    u64 re2[4], im2[4];
#pragma unroll
    for (int r = 0; r < 4; r++) { re2[r] = 0ULL; im2[r] = 0ULL; }

    const float* U0  = U + i0*132;
    const float* V0  = V + i0*132;
    const float* Tcp = Tc + l0;
    const float* Tsp = Ts + l0;
#pragma unroll 3
    for (int w = 0; w < 129; w++) {
        u64 cd = *(const u64*)&Tcp[w*34];            // packed (cos_l0, cos_l0+1)
        fma2(re2[0], cd, dup2(U0[w]));
        fma2(re2[1], cd, dup2(U0[132+w]));
        fma2(re2[2], cd, dup2(U0[264+w]));
        fma2(re2[3], cd, dup2(U0[396+w]));
    }
#pragma unroll 4
    for (int w = 0; w < 128; w++) {
        u64 sd = *(const u64*)&Tsp[w*34];            // packed (-sin_l0, -sin_l0+1)
        fma2(im2[0], sd, dup2(V0[w]));
        fma2(im2[1], sd, dup2(V0[132+w]));
        fma2(im2[2], sd, dup2(V0[264+w]));
        fma2(im2[3], sd, dup2(V0[396+w]));
    }
#pragma unroll
    for (int r = 0; r < 4; r++) {
        float2 rr = unpk2(re2[r]);
        float2 mm = unpk2(im2[r]);
        size_t idx = (((size_t)(b*64 + i0 + r) * 256 + h) * 64) + 2*l0;
        *(float4*)&g_Xw[idx] = make_float4(rr.x, mm.x, rr.y, mm.y);
    }
}

// ---------------------------------------------------------------------------
// Stage B (f32x2 + h-parity fold).
// ---------------------------------------------------------------------------
__global__ __launch_bounds__(256) void stageB() {
    __shared__ ulonglong2 twp[256];   // 4 KB
    int tid = threadIdx.x;
    { float s, c; sincosf(6.283185307179586f * (float)tid * (1.0f/256.0f), &s, &c);
      twp[tid] = make_ulonglong2(pack2(c, -s), pack2(s, c)); }
    __syncthreads();
    int blk = blockIdx.x;                             // b*64+i
    const float2* Xp = (const float2*)(g_Xw) + (size_t)blk * HH * M1;
    int l  = tid & 31;
    int k0 = tid >> 5;
    float sg = (k0 & 1) ? -1.0f : 1.0f;               // (-1)^k, warp-uniform
    u64 acc2[4];
    int mt[4];
#pragma unroll
    for (int t = 0; t < 4; t++) { acc2[t] = 0ULL; mt[t] = 0; }
    for (int h = 0; h < 128; h++) {
        float2 xa = Xp[h*M1 + l];
        float2 xb = Xp[(h+128)*M1 + l];
        u64 zr2 = dup2(fmaf(sg, xb.x, xa.x));
        u64 zi2 = dup2(fmaf(sg, xb.y, xa.y));
#pragma unroll
        for (int t = 0; t < 4; t++) {
            ulonglong2 e = twp[mt[t]];                // broadcast LDS.128
            fma2(acc2[t], e.x, zr2);
            fma2(acc2[t], e.y, zi2);
            mt[t] = (mt[t] + k0 + (t << 3)) & 255;
        }
    }
    float2* Om = (float2*)g_Xm + (size_t)blk * (M0*M1);
#pragma unroll
    for (int t = 0; t < 4; t++) {
        int k = k0 + (t << 3);
        Om[k*M1 + l] = unpk2(acc2[t]);
    }
}

// ---------------------------------------------------------------------------
// Mode mix + gamma fold. W read coalesced from pre-transposed g_Wt[kl][p].
// ---------------------------------------------------------------------------
__global__ __launch_bounds__(256) void mixK() {
    __shared__ float2 Wsh[CI*CO];    // 32 KB
    __shared__ float2 Xsh[NB*CI];    //  8 KB
    int kl = blockIdx.x;
    int tid = threadIdx.x;
    const float4* wsrc = (const float4*)(g_Wt + (size_t)kl * 4096);
    for (int q = tid; q < 2048; q += 256)
        ((float4*)Wsh)[q] = wsrc[q];                  // coalesced 16B
    for (int p = tid; p < NB*CI; p += 256)
        Xsh[p] = ((const float2*)g_Xm)[(size_t)p*1024 + kl];
    __syncthreads();
#pragma unroll
    for (int q = 0; q < 4; q++) {
        int idx = tid + q*256;                        // b*64+o
        int b = idx >> 6, o = idx & 63;
        float yr = 0.f, yi = 0.f;
#pragma unroll 8
        for (int i = 0; i < CI; i++) {
            float2 xv = Xsh[(b << 6) + i];
            float2 wv = Wsh[(i << 6) + o];
            yr += xv.x*wv.x - xv.y*wv.y;
            yi += xv.x*wv.y + xv.y*wv.x;
        }
        float g = 1.0f + g_gamma[idx];
        ((float2*)g_Yb)[(size_t)idx*1024 + kl] = make_float2(g*yr, g*yi);
    }
}

// ---------------------------------------------------------------------------
// Stage C (f32x2, occupancy-fixed): grid NB*CO*4; block owns 64-h strip.
// ---------------------------------------------------------------------------
__global__ __launch_bounds__(256) void stageC() {
    __shared__ ulonglong2 twp[256];   // 4 KB
    __shared__ float2 Ysh[M0*M1];     // 8 KB
    int tid = threadIdx.x;
    { float s, c; sincosf(6.283185307179586f * (float)tid * (1.0f/256.0f), &s, &c);
      twp[tid] = make_ulonglong2(pack2(c, s), pack2(-s, c)); }
    int blk = blockIdx.x >> 2;                        // b*64+o
    int hq  = blockIdx.x & 3;
    const float2* Yp = (const float2*)g_Yb + (size_t)blk * (M0*M1);
    for (int p = tid; p < M0*M1; p += 256) Ysh[p] = Yp[p];
    __syncthreads();

    int l  = tid & 31;
    int h0 = (hq << 6) + (tid >> 5);                  // base h for this thread
    u64 acc2[8];
#pragma unroll
    for (int t = 0; t < 8; t++) acc2[t] = 0ULL;
    for (int k = 0; k < M0; k++) {
        float2 yv = Ysh[k*M1 + l];
        u64 yr2 = dup2(yv.x), yi2 = dup2(yv.y);
        int mm = (k * h0) & 255;
        int st = (k << 3) & 255;
#pragma unroll
        for (int t = 0; t < 8; t++) {
            ulonglong2 e = twp[mm];                   // warp-uniform broadcast
            fma2(acc2[t], e.x, yr2);
            fma2(acc2[t], e.y, yi2);
            mm = (mm + st) & 255;
        }
    }
    float2* Zp = (float2*)g_Z + (size_t)blk * HH * M1;
#pragma unroll
    for (int t = 0; t < 8; t++)
        Zp[(h0 + (t << 3))*M1 + l] = unpk2(acc2[t]);
}

// ---------------------------------------------------------------------------
// Fused inverse-w DFT + beta + bypass + GELU, specfinal5K skeleton with the
// (w, 256-w) mirror pair: cos shared, sin sign-flipped, so the spectral loop
// accumulates Sc = sum zzRe*cos and Ss = sum zzIm*sin ONCE (spectral fma2
// halves vs 5K), then col w = Sc+Ss, col 256-w = Sc-Ss. Bypass unchanged,
// accumulating into the combined registers. Column 128 (uncovered) handled
// by a 32-thread special path: cos(pi l)=(-1)^l, sin=0. t=0 duplicate col-0
// write is benign (Ss=0 there). Regs = 5K budget (32 u64 accs); (128,4).
// ---------------------------------------------------------------------------
__global__ __launch_bounds__(128, 4) void specfinal8K(const float* __restrict__ x,
                                                      const float* __restrict__ bw,
                                                      const float* __restrict__ bb,
                                                      float* __restrict__ out) {
    __shared__ __align__(16) float zzRe[32*32];   // [l][o2] 4KB (norm folded)
    __shared__ __align__(16) float zzIm[32*32];   // [l][o2] 4KB
    __shared__ __align__(16) float bwt [64*32];   // [i][o2] 8KB
    __shared__ __align__(16) float xsp [64];      // x[:,h,128]
    __shared__ __align__(16) float beta_s[32];
    int t = threadIdx.x;                          // 0..127
    int b     = blockIdx.x >> 9;
    int h     = (blockIdx.x >> 1) & 255;
    int obase = (blockIdx.x & 1) << 5;            // 0 or 32

    size_t xrow = (size_t)b * CI * HH * WW + (size_t)h * WW;
    for (int p = t; p < 2048; p += 128) {
        int i = p >> 5, o2 = p & 31;
        bwt[p] = bw[(size_t)(obase + o2) * 64 + i];
    }
    const float nrm = 1.0f / 65536.0f;
    for (int p = t; p < 1024; p += 128) {
        int o2 = p >> 5, l = p & 31;
        float2 v = ((const float2*)g_Z)[((size_t)(b*64 + obase + o2) * 256 + h) * 32 + l];
        zzRe[l*32 + o2] = v.x * (l ? 2.0f*nrm : nrm);
        zzIm[l*32 + o2] = v.y * (-2.0f*nrm);
    }
    if (t < 64) xsp[t] = x[xrow + (size_t)t * HH * WW + 128];
    if (t < 32) beta_s[t] = g_beta[b*64 + obase + t] + bb[obase + t];
    __syncthreads();

    u64 Sc[16], Ss[16];
#pragma unroll
    for (int p = 0; p < 16; p++) { Sc[p] = 0ULL; Ss[p] = 0ULL; }

    // Bypass prefetch (completes under spectral FFMA)
    int wA = t, wB = (256 - t) & 255;
    float clo[4], chi[4];
#pragma unroll
    for (int j = 0; j < 4; j++) {
        clo[j] = x[xrow + wA + (size_t)j * HH * WW];
        chi[j] = x[xrow + wB + (size_t)j * HH * WW];
    }

    // Spectral: rotation recurrence at angle 2*pi*t/256; 4 fma2 per og
    // (half of 5K), since the mirror column reuses Sc/Ss with a sign.
    float cr, sr;
    sincosf(6.283185307179586f * (float)t * (1.0f/256.0f), &sr, &cr);
    float c = 1.0f, s = 0.0f;
#pragma unroll
    for (int l = 0; l < 32; l++) {
        u64 cd = dup2(c), sd = dup2(s);
        const ulonglong2* zr = (const ulonglong2*)(zzRe + l*32);
        const ulonglong2* zi = (const ulonglong2*)(zzIm + l*32);
#pragma unroll
        for (int og = 0; og < 8; og++) {
            ulonglong2 zp = zr[og];               // LDS.128 broadcast
            ulonglong2 ip = zi[og];
            fma2(Sc[2*og], zp.x, cd); fma2(Sc[2*og+1], zp.y, cd);
            fma2(Ss[2*og], ip.x, sd); fma2(Ss[2*og+1], ip.y, sd);
        }
        float cn = c*cr - s*sr;
        float sn = s*cr + c*sr;
        c = cn; s = sn;
    }

    // Combine: Sc <- col wA accumulator, Ss <- col wB accumulator.
#pragma unroll
    for (int p = 0; p < 16; p++) {
        u64 a = add2(Sc[p], Ss[p]);
        u64 d = sub2(Sc[p], Ss[p]);
        Sc[p] = a; Ss[p] = d;
    }

    // Bypass: both columns share each bwt row. (2048 fma2, as 5K)
    for (int i = 0; i < CI; i += 4) {
        float nlo[4], nhi[4];
        if (i + 4 < CI) {
#pragma unroll
            for (int j = 0; j < 4; j++) {
                nlo[j] = x[xrow + wA + (size_t)(i + 4 + j) * HH * WW];
                nhi[j] = x[xrow + wB + (size_t)(i + 4 + j) * HH * WW];
            }
        }
#pragma unroll
        for (int j = 0; j < 4; j++) {
            u64 xl = dup2(clo[j]), xh = dup2(chi[j]);
            const ulonglong2* wr2 = (const ulonglong2*)(bwt + ((i + j) << 5));
#pragma unroll
            for (int og = 0; og < 8; og++) {
                ulonglong2 wp = wr2[og];          // LDS.128 broadcast
                fma2(Sc[2*og    ], wp.x, xl); fma2(Sc[2*og + 1], wp.y, xl);
                fma2(Ss[2*og    ], wp.x, xh); fma2(Ss[2*og + 1], wp.y, xh);
            }
        }
#pragma unroll
        for (int j = 0; j < 4; j++) { clo[j] = nlo[j]; chi[j] = nhi[j]; }
    }

    size_t ob = (size_t)b * CO * HH * WW + (size_t)obase * HH * WW
              + (size_t)h * WW;
#pragma unroll 4
    for (int p = 0; p < 16; p++) {
        u64 bp = *(const u64*)&beta_s[p << 1];
        float2 vA = unpk2(add2(Sc[p], bp));
        float2 vB = unpk2(add2(Ss[p], bp));
        size_t r0 = ob + (size_t)(2*p    ) * HH * WW;
        size_t r1 = ob + (size_t)(2*p + 1) * HH * WW;
        out[r0 + wA] = gelu_tanh(vA.x);  out[r1 + wA] = gelu_tanh(vA.y);
        out[r0 + wB] = gelu_tanh(vB.x);  out[r1 + wB] = gelu_tanh(vB.y);
    }

    // Special column w = 128: cos(pi*l) = (-1)^l, sin = 0.
    if (t < 32) {
        int o2 = t;
        float sre = 0.0f;
#pragma unroll
        for (int l = 0; l < 32; l += 2)
            sre += zzRe[l*32 + o2] - zzRe[(l+1)*32 + o2];
        float b0 = 0.f, b1v = 0.f, b2v = 0.f, b3 = 0.f;
#pragma unroll 4
        for (int i = 0; i < CI; i += 4) {
            b0  = fmaf(bwt[(i  )*32 + o2], xsp[i    ], b0);
            b1v = fmaf(bwt[(i+1)*32 + o2], xsp[i + 1], b1v);
            b2v = fmaf(bwt[(i+2)*32 + o2], xsp[i + 2], b2v);
            b3  = fmaf(bwt[(i+3)*32 + o2], xsp[i + 3], b3);
        }
        float val = sre + (b0 + b1v) + (b2v + b3) + beta_s[o2];
        out[ob + (size_t)o2 * HH * WW + 128] = gelu_tanh(val);
    }
}

// ---------------------------------------------------------------------------
extern "C" void kernel_launch(void* const* d_in, const int* in_sizes, int n_in,
                              void* d_out, int out_size) {
    const float* x      = (const float*)d_in[0];
    const float* t_emb  = (const float*)d_in[1];
    const float* w_real = (const float*)d_in[2];
    const float* w_imag = (const float*)d_in[3];
    const float* fw1    = (const float*)d_in[4];
    const float* fb1    = (const float*)d_in[5];
    const float* fw2    = (const float*)d_in[6];
    const float* fb2    = (const float*)d_in[7];
    const float* bw     = (const float*)d_in[8];
    const float* bb     = (const float*)d_in[9];
    float* out = (float*)d_out;

    const int smemA = A3_SMEM * sizeof(float);                        // 102536
    cudaFuncSetAttribute(stageA5, cudaFuncAttributeMaxDynamicSharedMemorySize, smemA);

    stageA5<<<4097, 256, smemA>>>(x, w_real, w_imag, t_emb,
                                  fw1, fb1, fw2, fb2);                // 1
    stageB<<<NB*CI, 256>>>();                                         // 2
    mixK<<<M0*M1, 256>>>();                                           // 3
    stageC<<<NB*CO*4, 256>>>();                                       // 4 <- profiled
    specfinal8K<<<NB*HH*2, 128>>>(x, bw, bb, out);                    // 5
}